// round 9
// baseline (speedup 1.0000x reference)
#include <cuda_runtime.h>
#include <cuda_bf16.h>
#include <cstdint>
#include <float.h>

#define DINL __device__ __forceinline__

// ---------------- scratch (__device__ globals; no allocs allowed) ----------------
__device__ __nv_bfloat16 g_B[128 * 512];        // W^T bf16, [e][k] k-contiguous
__device__ float g_WT[128 * 512];               // W^T fp32, [e][k] (for exact recompute)
__device__ float g_cand[1024 * 128 * 10];       // per-(rowchunk,e): 5 max (desc) + 5 min (asc)
__device__ int   g_candIdx[1024 * 128 * 10];    // row-in-batch indices for the above
__device__ float g_pooled[32 * 128];

// ---------------- helpers ----------------
DINL uint32_t smem_u32(const void* p) {
    uint32_t a;
    asm("{ .reg .u64 t; cvta.to.shared.u64 t, %1; cvt.u32.u64 %0, t; }" : "=r"(a) : "l"(p));
    return a;
}

DINL void ldmatrix4(uint32_t& r0, uint32_t& r1, uint32_t& r2, uint32_t& r3, uint32_t addr) {
    asm volatile("ldmatrix.sync.aligned.m8n8.x4.shared.b16 {%0,%1,%2,%3}, [%4];"
                 : "=r"(r0), "=r"(r1), "=r"(r2), "=r"(r3) : "r"(addr));
}

DINL void mma16816(float* c, const uint32_t* a, uint32_t b0, uint32_t b1) {
    asm volatile(
        "mma.sync.aligned.m16n8k16.row.col.f32.bf16.bf16.f32 "
        "{%0,%1,%2,%3}, {%4,%5,%6,%7}, {%8,%9}, {%0,%1,%2,%3};"
        : "+f"(c[0]), "+f"(c[1]), "+f"(c[2]), "+f"(c[3])
        : "r"(a[0]), "r"(a[1]), "r"(a[2]), "r"(a[3]), "r"(b0), "r"(b1));
}

DINL void cp_async16(uint32_t dst, const void* src) {
    asm volatile("cp.async.cg.shared.global [%0], [%1], 16;" :: "r"(dst), "l"(src) : "memory");
}
DINL void cp_commit() { asm volatile("cp.async.commit_group;" ::: "memory"); }
DINL void cp_wait1()  { asm volatile("cp.async.wait_group 1;" ::: "memory"); }

DINL uint32_t packbf(float x, float y) {
    __nv_bfloat162 p = __floats2bfloat162_rn(x, y);
    return *(uint32_t*)&p;
}

// sorted-5 insertion, max side (v0>=..>=v4)
DINL void ins5max(float v, int i, float& v0, int& i0, float& v1, int& i1,
                  float& v2, int& i2, float& v3, int& i3, float& v4, int& i4) {
    if (v > v4) {
        if (v > v2) {
            if (v > v0)      { v4=v3;i4=i3; v3=v2;i3=i2; v2=v1;i2=i1; v1=v0;i1=i0; v0=v;i0=i; }
            else if (v > v1) { v4=v3;i4=i3; v3=v2;i3=i2; v2=v1;i2=i1; v1=v;i1=i; }
            else             { v4=v3;i4=i3; v3=v2;i3=i2; v2=v;i2=i; }
        } else {
            if (v > v3)      { v4=v3;i4=i3; v3=v;i3=i; }
            else             { v4=v;i4=i; }
        }
    }
}
// sorted-5 insertion, min side (v0<=..<=v4)
DINL void ins5min(float v, int i, float& v0, int& i0, float& v1, int& i1,
                  float& v2, int& i2, float& v3, int& i3, float& v4, int& i4) {
    if (v < v4) {
        if (v < v2) {
            if (v < v0)      { v4=v3;i4=i3; v3=v2;i3=i2; v2=v1;i2=i1; v1=v0;i1=i0; v0=v;i0=i; }
            else if (v < v1) { v4=v3;i4=i3; v3=v2;i3=i2; v2=v1;i2=i1; v1=v;i1=i; }
            else             { v4=v3;i4=i3; v3=v2;i3=i2; v2=v;i2=i; }
        } else {
            if (v < v3)      { v4=v3;i4=i3; v3=v;i3=i; }
            else             { v4=v;i4=i; }
        }
    }
}

// ---------------- kernel 1: W [512,128] fp32 -> g_B bf16 + g_WT fp32 ([e][k]) ----------------
__global__ void prep_B_kernel(const float* __restrict__ W) {
    int idx = blockIdx.x * 256 + threadIdx.x;   // 65536
    int k = idx >> 7, e = idx & 127;
    float v = W[idx];
    g_B[e * 512 + k] = __float2bfloat16(v);
    g_WT[e * 512 + k] = v;
}

// ---------------- kernel 2: occupancy-3 bf16 HMMA GEMM + top5/bot5 ----------------
// CTA: 128 rows x 64 e (cta = rowchunk*2 + ehalf). 256 threads, 8 warps, warp tile 32x32.
// K=512 in 16 chunks of 32; 3-stage cp.async pipeline (prefetch distance 2).
static constexpr int A32_STAGE = 16384;  // 128 rows x 32 k fp32 (128B rows, XOR-swizzled)
static constexpr int B_STAGE   = 4096;   // 64 e x 32 k bf16 (64B rows, XOR-swizzled)
static constexpr int OFF_A32 = 0;                             // 3 stages: 0..49152
static constexpr int OFF_B   = 3 * A32_STAGE;                 // 49152, 3 stages: ..61440
static constexpr int SM_BYTES = OFF_B + 3 * B_STAGE;          // 61440 (>= 34816 epilogue)

__global__ void __launch_bounds__(256, 3) gemm_pool_kernel(const float* __restrict__ x) {
    extern __shared__ __align__(128) char smem[];
    const uint32_t sb = smem_u32(smem);
    const int tid = threadIdx.x, lane = tid & 31, wid = tid >> 5;
    const int cta = blockIdx.x;
    const int chunkIdx = cta >> 1;            // row chunk 0..1023
    const int ehalf = cta & 1;                // e half: 0 -> e 0..63, 1 -> e 64..127
    const float* xg = x + (size_t)chunkIdx * 128 * 512;

    // ---- cp.async staging of one K32 chunk (A: 1024x16B fp32, B: 256x16B bf16) ----
    #define ISSUE_CHUNK(kc, st)                                                        \
    {                                                                                  \
        const uint32_t a32 = sb + OFF_A32 + (st) * A32_STAGE;                          \
        const uint32_t bbb = sb + OFF_B + (st) * B_STAGE;                              \
        _Pragma("unroll")                                                              \
        for (int i = 0; i < 4; i++) {                                                  \
            int u = tid + 256 * i;                                                     \
            int r = u >> 3, c = u & 7;                                                 \
            uint32_t off = (uint32_t)(r * 128 + ((c ^ (r & 7)) << 4));                 \
            cp_async16(a32 + off, xg + (size_t)r * 512 + (kc) * 32 + c * 4);           \
        }                                                                              \
        {                                                                              \
            int el = tid >> 2, c = tid & 3;  /* el 0..63 */                            \
            uint32_t off = (uint32_t)(el * 64 + ((c ^ ((el >> 1) & 3)) << 4));         \
            cp_async16(bbb + off,                                                      \
                       (const char*)g_B + (ehalf * 64 + el) * 1024 + (kc) * 64 + c * 16); \
        }                                                                              \
        cp_commit();                                                                   \
    }

    // ---- accumulators: warp tile 32(m) x 32(n), fp32 accumulate ----
    const int m0 = (wid & 3) * 32;
    const int n0 = (wid >> 2) * 32;           // local e offset (0 or 32)
    float acc[8][4];
    #pragma unroll
    for (int i = 0; i < 8; i++)
        #pragma unroll
        for (int j = 0; j < 4; j++) acc[i][j] = 0.f;

    // prologue: chunks 0,1 in flight
    ISSUE_CHUNK(0, 0);
    ISSUE_CHUNK(1, 1);

    // per-thread constant A-fragment addressing pieces
    const int arow = lane >> 2;               // row-in-16 (0..7)
    const uint32_t arem = (lane & 1) * 8;     // byte 0/8 within 16B chunk
    const uint32_t acsel = (lane & 3) >> 1;   // chunk select 0/1 within k16 block

    int st = 0;   // kc % 3
    for (int kc = 0; kc < 16; kc++) {
        cp_wait1();          // chunk kc complete (only newest group may be pending)
        __syncthreads();     // publish chunk kc; all threads past MMA(kc-1)

        const char* Ab = smem + OFF_A32 + st * A32_STAGE;
        const uint32_t Bb = sb + OFF_B + st * B_STAGE;

        #pragma unroll
        for (int ks = 0; ks < 2; ks++) {
            // --- A fragments: LDS.64 fp32 + convert (canonical m16n8k16 A layout) ---
            uint32_t a[2][4];
            #pragma unroll
            for (int mi = 0; mi < 2; mi++) {
                const int r = m0 + mi * 16 + arow;
                const int rx = r & 7;                    // (r+8)&7 == rx
                const uint32_t clo = ks * 4 + acsel;
                const char* rbase = Ab + r * 128;
                float2 p00 = *(const float2*)(rbase + ((clo ^ rx) << 4) + arem);
                float2 p10 = *(const float2*)(rbase + 1024 + ((clo ^ rx) << 4) + arem);
                float2 p01 = *(const float2*)(rbase + (((clo + 2) ^ rx) << 4) + arem);
                float2 p11 = *(const float2*)(rbase + 1024 + (((clo + 2) ^ rx) << 4) + arem);
                a[mi][0] = packbf(p00.x, p00.y);
                a[mi][1] = packbf(p10.x, p10.y);
                a[mi][2] = packbf(p01.x, p01.y);
                a[mi][3] = packbf(p11.x, p11.y);
            }
            // --- B fragments via ldmatrix ---
            const int ch = ks * 2 + (lane >> 4);
            uint32_t bq[2][4];
            #pragma unroll
            for (int nb = 0; nb < 2; nb++) {
                int el = n0 + nb * 16 + (lane & 15);
                uint32_t off = (uint32_t)(el * 64 + ((ch ^ ((el >> 1) & 3)) << 4));
                ldmatrix4(bq[nb][0], bq[nb][1], bq[nb][2], bq[nb][3], Bb + off);
            }
            #pragma unroll
            for (int mi = 0; mi < 2; mi++)
                #pragma unroll
                for (int ni = 0; ni < 4; ni++) {
                    int nb = ni >> 1, h = ni & 1;
                    mma16816(acc[mi * 4 + ni], a[mi], bq[nb][h], bq[nb][h + 2]);
                }

            // de-burst: issue next chunk's copies between the two ks halves
            if (ks == 0) {
                if (kc + 2 < 16) { int stn = st + 2; if (stn >= 3) stn -= 3; ISSUE_CHUNK(kc + 2, stn); }
                else             { cp_commit(); }   // empty group keeps wait accounting
            }
        }

        st = (st + 1 == 3) ? 0 : st + 1;
    }
    __syncthreads();   // all MMA reads done before smem reuse

    // ---- epilogue: acc -> smem f[128][68], then per-e top5/bot5 scan ----
    float* fb = (float*)smem;
    #pragma unroll
    for (int mi = 0; mi < 2; mi++)
        #pragma unroll
        for (int ni = 0; ni < 4; ni++) {
            int r = m0 + mi * 16 + (lane >> 2);
            int c = n0 + ni * 8 + (lane & 3) * 2;
            float* a4 = acc[mi * 4 + ni];
            fb[r * 68 + c] = a4[0];
            fb[r * 68 + c + 1] = a4[1];
            fb[(r + 8) * 68 + c] = a4[2];
            fb[(r + 8) * 68 + c + 1] = a4[3];
        }
    __syncthreads();

    if (tid < 64) {
        const int el = tid;
        float t0=-FLT_MAX,t1=-FLT_MAX,t2=-FLT_MAX,t3=-FLT_MAX,t4=-FLT_MAX;
        int   a0=0,a1=0,a2=0,a3=0,a4=0;
        float u0=FLT_MAX,u1=FLT_MAX,u2=FLT_MAX,u3=FLT_MAX,u4=FLT_MAX;
        int   b0=0,b1=0,b2=0,b3i=0,b4=0;
        const int rbase = (chunkIdx & 31) * 128;   // row-in-batch offset
        for (int r = 0; r < 128; r++) {
            float v = fb[r * 68 + el];
            ins5max(v, rbase + r, t0,a0, t1,a1, t2,a2, t3,a3, t4,a4);
            ins5min(v, rbase + r, u0,b0, u1,b1, u2,b2, u3,b3i, u4,b4);
        }
        const int eg = ehalf * 64 + el;
        size_t o = ((size_t)chunkIdx * 128 + eg) * 10;
        g_cand[o+0]=t0; g_cand[o+1]=t1; g_cand[o+2]=t2; g_cand[o+3]=t3; g_cand[o+4]=t4;
        g_cand[o+5]=u0; g_cand[o+6]=u1; g_cand[o+7]=u2; g_cand[o+8]=u3; g_cand[o+9]=u4;
        g_candIdx[o+0]=a0; g_candIdx[o+1]=a1; g_candIdx[o+2]=a2; g_candIdx[o+3]=a3; g_candIdx[o+4]=a4;
        g_candIdx[o+5]=b0; g_candIdx[o+6]=b1; g_candIdx[o+7]=b2; g_candIdx[o+8]=b3i; g_candIdx[o+9]=b4;
    }
    #undef ISSUE_CHUNK
}

// ---------------- kernel 3: merge chunks, exact fp32 recompute, pool ----------------
// grid = 4096 (b*128+e), block = 64 (warp0: max side, warp1: min side)
__global__ void merge_pool_kernel(const float* __restrict__ x) {
    const int blk = blockIdx.x;
    const int b = blk >> 7, e = blk & 127;
    const int tid = threadIdx.x, lane = tid & 31, w = tid >> 5;
    __shared__ int s_idx[10];
    __shared__ float s_exact[10];
    __shared__ float s_wcol[512];

    // stage this e's fp32 W column (contiguous in g_WT) into smem
    {
        const float4* wt = (const float4*)(g_WT + (size_t)e * 512);
        ((float4*)s_wcol)[tid] = wt[tid];
        ((float4*)s_wcol)[tid + 64] = wt[tid + 64];
    }

    // phase 1: each lane owns one of 32 chunks; warp-merge its sorted-5 lists -> global top5
    {
        size_t base = (((size_t)(b * 32 + lane)) * 128 + e) * 10 + (w ? 5 : 0);
        float v0, v1, v2, v3, v4;
        int j0, j1, j2, j3, j4;
        v0 = g_cand[base+0]; v1 = g_cand[base+1]; v2 = g_cand[base+2];
        v3 = g_cand[base+3]; v4 = g_cand[base+4];
        j0 = g_candIdx[base+0]; j1 = g_candIdx[base+1]; j2 = g_candIdx[base+2];
        j3 = g_candIdx[base+3]; j4 = g_candIdx[base+4];
        if (w) { v0 = -v0; v1 = -v1; v2 = -v2; v3 = -v3; v4 = -v4; }  // min side: negate -> desc keys

        #pragma unroll
        for (int r = 0; r < 5; r++) {
            float cur = v0;
            float m = cur;
            #pragma unroll
            for (int s = 16; s; s >>= 1) m = fmaxf(m, __shfl_xor_sync(0xffffffffu, m, s));
            unsigned ball = __ballot_sync(0xffffffffu, cur == m);
            int win = __ffs(ball) - 1;
            int widx = __shfl_sync(0xffffffffu, j0, win);
            if (lane == 0) s_idx[w * 5 + r] = widx;
            if (lane == win) { v0=v1; j0=j1; v1=v2; j1=j2; v2=v3; j2=j3; v3=v4; j3=j4; v4=-FLT_MAX; }
        }
    }
    __syncthreads();

    // phase 2: exact fp32 dot for each candidate (warp handles its 5), W column from smem
    for (int c = 0; c < 5; c++) {
        int idx = s_idx[w * 5 + c];
        const float* xr = x + ((size_t)b * 4096 + idx) * 512;
        float s = 0.f;
        #pragma unroll
        for (int k = lane; k < 512; k += 32) s = fmaf(xr[k], s_wcol[k], s);
        #pragma unroll
        for (int sh = 16; sh; sh >>= 1) s += __shfl_xor_sync(0xffffffffu, s, sh);
        if (lane == 0) s_exact[w * 5 + c] = s;
    }
    __syncthreads();

    // phase 3: exact top3 + bottom3
    if (tid == 0) {
        float mx[5], mn[5];
        #pragma unroll
        for (int i = 0; i < 5; i++) { mx[i] = s_exact[i]; mn[i] = s_exact[5 + i]; }
        float pmax = 0.f, pmin = 0.f;
        #pragma unroll
        for (int pick = 0; pick < 3; pick++) {
            int bi = 0;
            #pragma unroll
            for (int i = 1; i < 5; i++) if (mx[i] > mx[bi]) bi = i;
            pmax += mx[bi]; mx[bi] = -FLT_MAX;
            int si = 0;
            #pragma unroll
            for (int i = 1; i < 5; i++) if (mn[i] < mn[si]) si = i;
            pmin += mn[si]; mn[si] = FLT_MAX;
        }
        g_pooled[b * 128 + e] = pmax + pmin;
    }
}

// ---------------- kernel 4: L2 normalize ----------------
__global__ void normalize_kernel(float* __restrict__ out) {
    const int b = blockIdx.x, e = threadIdx.x;
    float p = g_pooled[b * 128 + e];
    __shared__ float sq[128];
    sq[e] = p * p;
    __syncthreads();
    for (int s = 64; s; s >>= 1) {
        if (e < s) sq[e] += sq[e + s];
        __syncthreads();
    }
    out[b * 128 + e] = p * rsqrtf(fmaxf(sq[0], 1e-12f));
}

// ---------------- launch ----------------
extern "C" void kernel_launch(void* const* d_in, const int* in_sizes, int n_in,
                              void* d_out, int out_size) {
    (void)in_sizes; (void)n_in; (void)out_size;
    const float* x = (const float*)d_in[0];   // [32,64,64,512] fp32
    const float* W = (const float*)d_in[1];   // [512,128] fp32
    float* out = (float*)d_out;               // [32,128] fp32

    cudaFuncSetAttribute(gemm_pool_kernel,
                         cudaFuncAttributeMaxDynamicSharedMemorySize, SM_BYTES);

    prep_B_kernel<<<256, 256>>>(W);                 // global launch idx 0
    gemm_pool_kernel<<<2048, 256, SM_BYTES>>>(x);   // idx 1
    merge_pool_kernel<<<4096, 64>>>(x);             // idx 2
    // PROFILING PROBE at idx 3 (ncu captures global launch #3): idempotent re-run of
    // one full 3-CTA/SM wave (444 CTAs); rewrites identical g_cand values.
    gemm_pool_kernel<<<444, 256, SM_BYTES>>>(x);    // idx 3 (probe)
    normalize_kernel<<<32, 128>>>(out);             // idx 4
}